// round 1
// baseline (speedup 1.0000x reference)
#include <cuda_runtime.h>

#define HBV   20
#define DV    40
#define WPAD  28          // weight row pad: 112B, 16B-aligned, bank-conflict-free
#define WARPS 4

__global__ __launch_bounds__(128)
void ende_kernel(const float* __restrict__ x,
                 const float* __restrict__ w1g,
                 const float* __restrict__ w2g,
                 const float* __restrict__ w3g,
                 const float* __restrict__ w4g,
                 float* __restrict__ out_vec,
                 float* __restrict__ out_jt)
{
    __shared__ __align__(16) float sw1[HBV * WPAD];
    __shared__ __align__(16) float sw2[HBV * WPAD];
    __shared__ __align__(16) float sw3[HBV * WPAD];
    __shared__ __align__(16) float sw4[HBV * WPAD];
    __shared__ __align__(16) float p1s[WARPS][HBV];
    __shared__ __align__(16) float s2s[WARPS][HBV];
    __shared__ float2 b12s[WARPS][HBV];
    __shared__ float2 a34s[WARPS][HBV];
    __shared__ __align__(16) float jjb[WARPS][HBV * HBV];

    const int tid = threadIdx.x;

    // Stage weights into padded smem (once per block)
    for (int idx = tid; idx < HBV * HBV; idx += 128) {
        int r = idx / HBV, c = idx % HBV;
        sw1[r * WPAD + c] = w1g[idx];
        sw2[r * WPAD + c] = w2g[idx];
        sw3[r * WPAD + c] = w3g[idx];
        sw4[r * WPAD + c] = w4g[idx];
    }
    __syncthreads();

    const int w = tid >> 5;
    const int l = tid & 31;
    const long long b = (long long)blockIdx.x * WARPS + w;

    const float* xr = x + b * DV;
    float p1_own = 0.f, p2_own = 0.f;
    if (l < HBV) {
        p1_own = xr[l];
        p2_own = xr[HBV + l];
        p1s[w][l] = p1_own;
    }
    __syncwarp();

    // ---- Stage A: f1 = tanh(W1 p1), f2 = tanh(W2 p1) ----
    float e2_own = 0.f, s2_own = 0.f;
    if (l < HBV) {
        float a1 = 0.f, a2 = 0.f;
        const float4* r1 = (const float4*)(sw1 + l * WPAD);
        const float4* r2 = (const float4*)(sw2 + l * WPAD);
        const float4* pv = (const float4*)(p1s[w]);
        #pragma unroll
        for (int g = 0; g < 5; g++) {
            float4 A = r1[g], Bv = r2[g], P = pv[g];
            a1 = fmaf(A.x,  P.x, a1); a1 = fmaf(A.y,  P.y, a1);
            a1 = fmaf(A.z,  P.z, a1); a1 = fmaf(A.w,  P.w, a1);
            a2 = fmaf(Bv.x, P.x, a2); a2 = fmaf(Bv.y, P.y, a2);
            a2 = fmaf(Bv.z, P.z, a2); a2 = fmaf(Bv.w, P.w, a2);
        }
        float f1 = tanhf(a1);
        float f2 = tanhf(a2);
        e2_own = expf(f2);
        float p2e = p2_own * e2_own;
        s2_own = p2e + f1;
        s2s[w][l]  = s2_own;
        b12s[w][l] = make_float2(1.f - f1 * f1, p2e * (1.f - f2 * f2));
    }
    __syncwarp();

    // ---- Stage B: f3 = tanh(W3 s2), f4 = tanh(W4 s2) + out vector ----
    float e4_own = 0.f;
    if (l < HBV) {
        float a3 = 0.f, a4 = 0.f;
        const float4* r3 = (const float4*)(sw3 + l * WPAD);
        const float4* r4 = (const float4*)(sw4 + l * WPAD);
        const float4* sv = (const float4*)(s2s[w]);
        #pragma unroll
        for (int g = 0; g < 5; g++) {
            float4 A = r3[g], Bv = r4[g], S = sv[g];
            a3 = fmaf(A.x,  S.x, a3); a3 = fmaf(A.y,  S.y, a3);
            a3 = fmaf(A.z,  S.z, a3); a3 = fmaf(A.w,  S.w, a3);
            a4 = fmaf(Bv.x, S.x, a4); a4 = fmaf(Bv.y, S.y, a4);
            a4 = fmaf(Bv.z, S.z, a4); a4 = fmaf(Bv.w, S.w, a4);
        }
        float f3 = tanhf(a3);
        float f4 = tanhf(a4);
        e4_own = expf(f4);
        float s1e = p1_own * e4_own;
        float t1  = s1e + f3;
        a34s[w][l] = make_float2(1.f - f3 * f3, s1e * (1.f - f4 * f4));
        out_vec[b * DV + l]       = t1;
        out_vec[b * DV + HBV + l] = s2_own;
    }
    __syncwarp();

    float* jt = out_jt + b * (DV * DV);

    // ---- J21 (bottom-left, direct store; column cached in regs) and
    //      bottom-right diag(e2); JJ12 (scaled -> top-right, raw -> smem) ----
    float J21r[HBV];
    if (l < HBV) {
        #pragma unroll
        for (int k = 0; k < HBV; k++) {
            float2 c = b12s[w][k];
            float v = fmaf(c.x, sw1[k * WPAD + l], c.y * sw2[k * WPAD + l]);
            J21r[k] = v;
            jt[(HBV + k) * DV + l]       = v;
            jt[(HBV + k) * DV + HBV + l] = (l == k) ? e2_own : 0.f;
        }
        #pragma unroll
        for (int i = 0; i < HBV; i++) {
            float2 c = a34s[w][i];
            float v = fmaf(c.x, sw3[i * WPAD + l], c.y * sw4[i * WPAD + l]);
            jjb[w][i * HBV + l]    = v;          // raw JJ12 for the matmul
            jt[i * DV + HBV + l]   = v * e2_own; // top-right: JJ12 * diag(e2)
        }
    }
    __syncwarp();

    // ---- Top-left: diag(e4) + JJ12 @ J21 ----
    if (l < HBV) {
        #pragma unroll 4
        for (int i = 0; i < HBV; i++) {
            const float4* rv = (const float4*)(jjb[w] + i * HBV);
            float m = 0.f;
            #pragma unroll
            for (int g = 0; g < 5; g++) {
                float4 c = rv[g];
                m = fmaf(c.x, J21r[4 * g + 0], m);
                m = fmaf(c.y, J21r[4 * g + 1], m);
                m = fmaf(c.z, J21r[4 * g + 2], m);
                m = fmaf(c.w, J21r[4 * g + 3], m);
            }
            if (i == l) m += e4_own;
            jt[i * DV + l] = m;
        }
    }
}

extern "C" void kernel_launch(void* const* d_in, const int* in_sizes, int n_in,
                              void* d_out, int out_size) {
    const float* x  = (const float*)d_in[0];
    const float* w1 = (const float*)d_in[1];
    const float* w2 = (const float*)d_in[2];
    const float* w3 = (const float*)d_in[3];
    const float* w4 = (const float*)d_in[4];

    const int B = in_sizes[0] / DV;          // 65536
    float* out_vec = (float*)d_out;          // tuple element 0: (B,1,40)
    float* out_jt  = out_vec + (size_t)B * DV; // tuple element 1: (B,40,40)

    ende_kernel<<<B / WARPS, 128>>>(x, w1, w2, w3, w4, out_vec, out_jt);
}